// round 8
// baseline (speedup 1.0000x reference)
#include <cuda_runtime.h>
#include <cuda_bf16.h>
#include <cstdint>

// ---------------- problem constants ----------------
#define Dk 256
#define Tk 2048
#define Bk 16
#define Kk 8192
#define Nk 32768            // B*T
#define QCOUNT 8388608      // B*D*T

// ---------------- pass1 GEMM config ----------------
#define GM 256              // rows per CTA
#define GN 128              // codes per chunk
#define NCHUNKS 64          // 8192/128
#define KW 64               // k elements per stage
#define SPC 4               // stages per chunk (256/64)
#define NST (NCHUNKS * SPC) // 256
#define NBUF 3              // cp.async ring depth
#define A_STRIDE 264        // 256 + 8 pad (elements)
#define B_STRIDE 72         // 64 + 8 pad (elements)
#define B_STAGE_BYTES (128 * B_STRIDE * 2)   // 18432

// smem layout (bytes)
#define SM_A    0
#define SM_B    (GM * A_STRIDE * 2)                  // 135168
#define SM_OCT  (SM_B + NBUF * B_STAGE_BYTES)        // 190464 ; float[256][20]
#define SM_GM   (SM_OCT + 256 * 20 * 4)              // 210944 ; float[256][5]
#define SMEM_TOTAL (SM_GM + 256 * 5 * 4)             // 216064

#define TAU 1.5e-4f

// ---------------- device scratch (no allocs allowed) ----------------
__device__ __align__(16) __nv_bfloat16 g_A[(size_t)Nk * Dk];   // z transposed bf16 [n][d]
__device__ __align__(16) float         g_zt[(size_t)Nk * Dk];  // z transposed fp32 [n][d]
__device__ __align__(16) __nv_bfloat16 g_Bm[(size_t)Kk * Dk];  // emb bf16 [k][d]
__device__ __align__(16) float g_gmin[(size_t)Nk * 256];       // per-row 32-code-group min
__device__ __align__(16) float g_gmin8[(size_t)Nk * 1024];     // per-row 8-code octet min
__device__ float  g_enorm[Kk];
__device__ __align__(16) int g_idx[Nk];
__device__ double g_losspart[QCOUNT / 1024];

// ---------------- asm helpers ----------------
__device__ __forceinline__ uint32_t smem_u32(const void* p) {
    uint32_t a;
    asm("{ .reg .u64 t; cvta.to.shared.u64 t, %1; cvt.u32.u64 %0, t; }" : "=r"(a) : "l"(p));
    return a;
}
__device__ __forceinline__ void cp_async16(uint32_t dst, const void* src) {
    asm volatile("cp.async.cg.shared.global [%0], [%1], 16;"
                 :: "r"(dst), "l"(__cvta_generic_to_global(src)) : "memory");
}
__device__ __forceinline__ void cp_commit() {
    asm volatile("cp.async.commit_group;" ::: "memory");
}
__device__ __forceinline__ void cp_wait1() {
    asm volatile("cp.async.wait_group 1;" ::: "memory");
}
__device__ __forceinline__ void ldsm_x4(uint32_t& r0, uint32_t& r1, uint32_t& r2, uint32_t& r3,
                                        uint32_t addr) {
    asm volatile("ldmatrix.sync.aligned.m8n8.x4.shared.b16 {%0,%1,%2,%3}, [%4];"
                 : "=r"(r0), "=r"(r1), "=r"(r2), "=r"(r3) : "r"(addr));
}
__device__ __forceinline__ void mma_bf16(float* c, uint32_t a0, uint32_t a1, uint32_t a2,
                                         uint32_t a3, uint32_t b0, uint32_t b1) {
    asm volatile("mma.sync.aligned.m16n8k16.row.col.f32.bf16.bf16.f32 "
                 "{%0,%1,%2,%3}, {%4,%5,%6,%7}, {%8,%9}, {%0,%1,%2,%3};"
                 : "+f"(c[0]), "+f"(c[1]), "+f"(c[2]), "+f"(c[3])
                 : "r"(a0), "r"(a1), "r"(a2), "r"(a3), "r"(b0), "r"(b1));
}

// ---------------- prep: emb -> bf16 ----------------
__global__ __launch_bounds__(256)
void prepB_kernel(const float* __restrict__ emb) {
    int i = blockIdx.x * 256 + threadIdx.x;
    g_Bm[i] = __float2bfloat16(emb[i]);
}

// ---------------- prep: emb row norms ----------------
__global__ void enorm_kernel(const float* __restrict__ emb) {
    int warp = (blockIdx.x * blockDim.x + threadIdx.x) >> 5;
    int lane = threadIdx.x & 31;
    if (warp >= Kk) return;
    const float* row = emb + (size_t)warp * Dk;
    float s = 0.f;
#pragma unroll
    for (int i = 0; i < Dk; i += 32) { float v = row[i + lane]; s += v * v; }
#pragma unroll
    for (int o = 16; o > 0; o >>= 1) s += __shfl_down_sync(0xffffffffu, s, o);
    if (lane == 0) g_enorm[warp] = s;
}

// ---------------- prep: transpose z -> [n][d] (bf16 + fp32) ----------------
__global__ void prepA_kernel(const float* __restrict__ z) {
    __shared__ float tile[32][33];
    int b = blockIdx.x >> 6;
    int t0 = (blockIdx.x & 63) * 32;
    int d0 = blockIdx.y * 32;
    int tx = threadIdx.x;
#pragma unroll
    for (int i = threadIdx.y; i < 32; i += 8)
        tile[i][tx] = z[((size_t)b * Dk + d0 + i) * Tk + t0 + tx];
    __syncthreads();
#pragma unroll
    for (int i = threadIdx.y; i < 32; i += 8) {
        int n = b * Tk + t0 + i;
        float v = tile[tx][i];
        g_A[(size_t)n * Dk + d0 + tx] = __float2bfloat16(v);
        g_zt[(size_t)n * Dk + d0 + tx] = v;
    }
}

// ---------------- pass1: bf16 HMMA GEMM (256x128 tile) + octet/group mins ----------------
__device__ __forceinline__ void b_stage_issue(uint32_t sb, int tid, int s3) {
    if (s3 < NST) {
        int cc = s3 >> 2, kk = s3 & 3;
        int buf = s3 % NBUF;
#pragma unroll
        for (int i = 0; i < 2; i++) {
            int idx = tid + i * 512;                 // 1024 x 16B = one 16KB stage
            int r = idx >> 3, ch = idx & 7;
            cp_async16(sb + SM_B + buf * B_STAGE_BYTES + (r * B_STRIDE + ch * 8) * 2,
                       g_Bm + ((size_t)cc * GN + r) * Dk + kk * KW + ch * 8);
        }
    }
    cp_commit();
}

__global__ __launch_bounds__(512, 1)
void pass1_gemm(void) {
    extern __shared__ __align__(16) char smem[];
    uint32_t sb = smem_u32(smem);
    float* oct_sm = (float*)(smem + SM_OCT);   // [256][20]
    float* gm_sm  = (float*)(smem + SM_GM);    // [256][5]

    int tid = threadIdx.x;
    int lane = tid & 31;
    int wid = tid >> 5;
    int warpN = wid & 3;      // 4 n-warps (32 cols each) == one 32-code group each
    int warpM = wid >> 2;     // 4 m-warps (64 rows each)
    int rowBase = blockIdx.x * GM;

    // ---- prologue: A resident + B stages 0..1 ----
    {
        const __nv_bfloat16* Ag = g_A + (size_t)rowBase * Dk;
#pragma unroll
        for (int i = 0; i < 16; i++) {
            int idx = tid + i * 512;               // 8192 x 16B
            int r = idx >> 5, ch = idx & 31;
            cp_async16(sb + SM_A + (r * A_STRIDE + ch * 8) * 2, Ag + (size_t)r * Dk + ch * 8);
        }
        b_stage_issue(sb, tid, 0);   // G0 = {A, B0}
        b_stage_issue(sb, tid, 1);   // G1 = {B1}
    }

    float acc[4][4][4];

    for (int c = 0; c < NCHUNKS; c++) {
#pragma unroll
        for (int i = 0; i < 4; i++)
#pragma unroll
            for (int j = 0; j < 4; j++)
#pragma unroll
                for (int e = 0; e < 4; e++) acc[i][j][e] = 0.f;

        for (int ks = 0; ks < SPC; ks++) {
            int s = c * SPC + ks;
            cp_wait1();
            __syncthreads();
            b_stage_issue(sb, tid, s + 2);

            uint32_t bbase = sb + SM_B + (s % NBUF) * B_STAGE_BYTES;
#pragma unroll
            for (int kh = 0; kh < 4; kh++) {
                uint32_t af[4][4];
                uint32_t bfr[4][2];
#pragma unroll
                for (int mt = 0; mt < 4; mt++) {
                    int row = warpM * 64 + mt * 16 + (lane & 15);
                    int col = ks * KW + kh * 16 + (lane >> 4) * 8;
                    ldsm_x4(af[mt][0], af[mt][1], af[mt][2], af[mt][3],
                            sb + SM_A + (row * A_STRIDE + col) * 2);
                }
#pragma unroll
                for (int pr = 0; pr < 2; pr++) {
                    int nrow = warpN * 32 + pr * 16 + (lane & 7) + ((lane & 16) ? 8 : 0);
                    int ncol = kh * 16 + (lane & 8);
                    uint32_t r0, r1, r2, r3;
                    ldsm_x4(r0, r1, r2, r3, bbase + (nrow * B_STRIDE + ncol) * 2);
                    bfr[pr * 2 + 0][0] = r0; bfr[pr * 2 + 0][1] = r1;
                    bfr[pr * 2 + 1][0] = r2; bfr[pr * 2 + 1][1] = r3;
                }
#pragma unroll
                for (int mt = 0; mt < 4; mt++)
#pragma unroll
                    for (int nt = 0; nt < 4; nt++)
                        mma_bf16(acc[mt][nt], af[mt][0], af[mt][1], af[mt][2], af[mt][3],
                                 bfr[nt][0], bfr[nt][1]);
            }
        }

        // ---- per-chunk epilogue: octet mins -> smem staging -> coalesced stores ----
        {
            float en8[8];
#pragma unroll
            for (int nt = 0; nt < 4; nt++)
#pragma unroll
                for (int e = 0; e < 2; e++)
                    en8[nt * 2 + e] =
                        __ldg(&g_enorm[c * GN + warpN * 32 + nt * 8 + (lane & 3) * 2 + e]);
#pragma unroll
            for (int mt = 0; mt < 4; mt++) {
#pragma unroll
                for (int h = 0; h < 2; h++) {
                    float v[4];
#pragma unroll
                    for (int nt = 0; nt < 4; nt++) {
                        float a = fmaf(-2.f, acc[mt][nt][h * 2 + 0], en8[nt * 2 + 0]);
                        float b = fmaf(-2.f, acc[mt][nt][h * 2 + 1], en8[nt * 2 + 1]);
                        v[nt] = fminf(a, b);
                        v[nt] = fminf(v[nt], __shfl_xor_sync(0xffffffffu, v[nt], 1));
                        v[nt] = fminf(v[nt], __shfl_xor_sync(0xffffffffu, v[nt], 2));
                    }
                    if ((lane & 3) == 0) {
                        int row = warpM * 64 + mt * 16 + (lane >> 2) + h * 8;
                        *(float4*)(oct_sm + row * 20 + warpN * 4) =
                            make_float4(v[0], v[1], v[2], v[3]);
                        gm_sm[row * 5 + warpN] =
                            fminf(fminf(v[0], v[1]), fminf(v[2], v[3]));
                    }
                }
            }
            __syncthreads();
            // coalesced write-out: 2 threads per row, 32B contiguous each
            {
                int row = tid >> 1, half = tid & 1;
                float4 a = *(float4*)(oct_sm + row * 20 + half * 8);
                float4 b = *(float4*)(oct_sm + row * 20 + half * 8 + 4);
                float* dst = g_gmin8 + (size_t)(rowBase + row) * 1024 + c * 16 + half * 8;
                *(float4*)dst = a;
                *(float4*)(dst + 4) = b;
                if (half == 0) {
                    float4 gm = make_float4(gm_sm[row * 5 + 0], gm_sm[row * 5 + 1],
                                            gm_sm[row * 5 + 2], gm_sm[row * 5 + 3]);
                    *(float4*)(g_gmin + (size_t)(rowBase + row) * 256 + c * 4) = gm;
                }
            }
            // next chunk's first-stage __syncthreads protects oct_sm/gm_sm reuse
        }
    }
}

// ---------------- pass2: exact fp32 refine at octet granularity ----------------
__global__ __launch_bounds__(256)
void refine_kernel(const float* __restrict__ emb, float* __restrict__ idx_out) {
    __shared__ __align__(16) float zsh[8][256];
    int lane = threadIdx.x & 31;
    int wid = threadIdx.x >> 5;
    int n = blockIdx.x * 8 + wid;

    // exact z row -> smem; zn in validated order
    float zn = 0.f;
#pragma unroll
    for (int i = 0; i < 8; i++) {
        float v = g_zt[(size_t)n * Dk + lane + 32 * i];
        zsh[wid][lane + 32 * i] = v;
        zn = fmaf(v, v, zn);
    }
#pragma unroll
    for (int o = 16; o > 0; o >>= 1) zn += __shfl_xor_sync(0xffffffffu, zn, o);
    __syncwarp();

    // 32-group mins + threshold
    float gmv[8];
    float m = 3.4e38f;
#pragma unroll
    for (int i = 0; i < 8; i++) {
        gmv[i] = g_gmin[(size_t)n * 256 + lane + 32 * i];
        m = fminf(m, gmv[i]);
    }
#pragma unroll
    for (int o = 16; o > 0; o >>= 1) m = fminf(m, __shfl_xor_sync(0xffffffffu, m, o));
    float thr = m + TAU;

    float bd = 3.4e38f;
    int bi = 0x7fffffff;
    int cq = lane >> 2;          // code within octet
    int p = lane & 3;            // quarter of d
    const float4* zv4 = (const float4*)zsh[wid];

#pragma unroll 1
    for (int i = 0; i < 8; i++) {
        unsigned mask = __ballot_sync(0xffffffffu, gmv[i] <= thr);
        while (mask) {
            int b = __ffs(mask) - 1;
            mask &= mask - 1;
            int g = i * 32 + b;                       // candidate 32-code group
            float4 o4 = *(const float4*)(g_gmin8 + (size_t)n * 1024 + g * 4);
            float om[4] = {o4.x, o4.y, o4.z, o4.w};
#pragma unroll 1
            for (int o = 0; o < 4; o++) {
                if (om[o] > thr) continue;
                int k = (g * 4 + o) * 8 + cq;          // this quad's code
                const float4* er4 = (const float4*)(emb + (size_t)k * Dk);
                float s0 = 0.f, s1 = 0.f, s2 = 0.f, s3 = 0.f;
#pragma unroll
                for (int j = 0; j < 16; j++) {
                    float4 e4 = er4[p + 4 * j];
                    float4 z4 = zv4[p + 4 * j];
                    s0 = fmaf(z4.x, e4.x, s0);
                    s1 = fmaf(z4.y, e4.y, s1);
                    s2 = fmaf(z4.z, e4.z, s2);
                    s3 = fmaf(z4.w, e4.w, s3);
                }
                float dot = (s0 + s1) + (s2 + s3);
                dot += __shfl_xor_sync(0xffffffffu, dot, 1);
                dot += __shfl_xor_sync(0xffffffffu, dot, 2);
                float d = (zn + g_enorm[k]) - 2.0f * dot;   // reference rounding pattern
                if (d < bd || (d == bd && k < bi)) { bd = d; bi = k; }
            }
        }
    }
    // warp lexicographic argmin (first-index tiebreak)
#pragma unroll
    for (int o = 16; o > 0; o >>= 1) {
        float od = __shfl_xor_sync(0xffffffffu, bd, o);
        int   oi = __shfl_xor_sync(0xffffffffu, bi, o);
        if (od < bd || (od == bd && oi < bi)) { bd = od; bi = oi; }
    }
    if (lane == 0) {
        g_idx[n] = bi;
        if (idx_out) idx_out[n] = (float)bi;
    }
}

// ---------------- gather quantized + loss partials (float4) ----------------
__global__ __launch_bounds__(256)
void quant_loss_kernel(const float* __restrict__ z, const float* __restrict__ emb,
                       float* __restrict__ qout) {
    __shared__ float wsum[8];
    int base = blockIdx.x * 1024 + threadIdx.x * 4;   // 4 consecutive t, same (b,d)
    int t = base & 2047;
    int d = (base >> 11) & 255;
    int b = base >> 19;
    int n = b * 2048 + t;
    int4 iv = *(const int4*)(g_idx + n);
    float4 zv = *(const float4*)(z + base);
    float4 q;
    q.x = emb[(size_t)iv.x * Dk + d];
    q.y = emb[(size_t)iv.y * Dk + d];
    q.z = emb[(size_t)iv.z * Dk + d];
    q.w = emb[(size_t)iv.w * Dk + d];
    *(float4*)(qout + base) = q;
    float dx = q.x - zv.x, dy = q.y - zv.y, dz = q.z - zv.z, dw = q.w - zv.w;
    float s = dx * dx + dy * dy + dz * dz + dw * dw;
#pragma unroll
    for (int o = 16; o > 0; o >>= 1) s += __shfl_xor_sync(0xffffffffu, s, o);
    if ((threadIdx.x & 31) == 0) wsum[threadIdx.x >> 5] = s;
    __syncthreads();
    if (threadIdx.x == 0) {
        double tot = 0.0;
#pragma unroll
        for (int w = 0; w < 8; w++) tot += (double)wsum[w];
        g_losspart[blockIdx.x] = tot;
    }
}

__global__ void loss_kernel(float* __restrict__ loss_out) {
    __shared__ double red[256];
    double s = 0.0;
    for (int i = threadIdx.x; i < QCOUNT / 1024; i += 256) s += g_losspart[i];
    red[threadIdx.x] = s;
    __syncthreads();
#pragma unroll
    for (int o = 128; o > 0; o >>= 1) {
        if (threadIdx.x < o) red[threadIdx.x] += red[threadIdx.x + o];
        __syncthreads();
    }
    if (threadIdx.x == 0)
        loss_out[0] = (float)(1.25 * (red[0] / (double)QCOUNT));
}

// ---------------- host launch ----------------
extern "C" void kernel_launch(void* const* d_in, const int* in_sizes, int n_in,
                              void* d_out, int out_size) {
    const float* z   = (const float*)d_in[0];
    const float* emb = (const float*)d_in[1];
    float* out = (float*)d_out;

    float* qout     = out;
    float* loss_out = nullptr;
    float* idx_out  = nullptr;
    if (out_size >= QCOUNT + 1 + Nk) {          // [quantized | loss | idx]
        loss_out = out + QCOUNT;
        idx_out  = out + QCOUNT + 1;
    } else if (out_size == QCOUNT + Nk) {
        idx_out = out + QCOUNT;
    } else if (out_size == QCOUNT + 1) {
        loss_out = out + QCOUNT;
    }

    static bool attr_set = false;
    if (!attr_set) {
        cudaFuncSetAttribute(pass1_gemm, cudaFuncAttributeMaxDynamicSharedMemorySize, SMEM_TOTAL);
        attr_set = true;
    }

    prepB_kernel<<<(Kk * Dk) / 256, 256>>>(emb);            // launch 0
    enorm_kernel<<<Kk / 8, 256>>>(emb);                     // launch 1
    prepA_kernel<<<dim3(Bk * (Tk / 32), Dk / 32), dim3(32, 8)>>>(z);  // launch 2
    pass1_gemm<<<Nk / GM, 512, SMEM_TOTAL>>>();             // launch 3 (ncu slot)
    refine_kernel<<<Nk / 8, 256>>>(emb, idx_out);           // launch 4
    quant_loss_kernel<<<QCOUNT / 1024, 256>>>(z, emb, qout);// launch 5
    if (loss_out) loss_kernel<<<1, 256>>>(loss_out);        // launch 6
}

// round 9
// speedup vs baseline: 1.0930x; 1.0930x over previous
#include <cuda_runtime.h>
#include <cuda_bf16.h>
#include <cstdint>

// ---------------- problem constants ----------------
#define Dk 256
#define Tk 2048
#define Bk 16
#define Kk 8192
#define Nk 32768            // B*T
#define QCOUNT 8388608      // B*D*T

// ---------------- pass1 GEMM config ----------------
#define GM 128              // rows per CTA-unit
#define GN 128              // codes per chunk
#define CPU_ 8              // chunks per unit (1024 codes)
#define SPCH 8              // stages per chunk (256/KW)
#define KW 32               // k elements per stage
#define NPAIRS 32           // 64 stages / 2
#define NBUF 4
#define A_STRIDE 264        // 256 + 8 pad (elements)
#define B_STRIDE 40         // 32 + 8 pad (elements)
#define B_STAGE_BYTES (128 * B_STRIDE * 2)   // 10240

// smem layout (bytes)
#define SM_A   0
#define SM_B   (GM * A_STRIDE * 2)                  // 67584
#define SMEM_TOTAL (SM_B + NBUF * B_STAGE_BYTES)    // 108544 (2 CTA/SM)

#define TAU 1.5e-4f

// ---------------- device scratch (no allocs allowed) ----------------
__device__ __align__(16) __nv_bfloat16 g_A[(size_t)Nk * Dk];   // z transposed bf16 [n][d]
__device__ __align__(16) float         g_zt[(size_t)Nk * Dk];  // z transposed fp32 [n][d]
__device__ __align__(16) __nv_bfloat16 g_Bm[(size_t)Kk * Dk];  // emb bf16 [k][d]
__device__ __align__(16) float g_gmin[(size_t)Nk * 256];       // per-row 32-code-group min
__device__ __align__(16) float g_gmin8[(size_t)Nk * 1024];     // per-row 8-code octet min
__device__ float  g_enorm[Kk];
__device__ __align__(16) int g_idx[Nk];
__device__ double g_losspart[QCOUNT / 1024];

// ---------------- asm helpers ----------------
__device__ __forceinline__ uint32_t smem_u32(const void* p) {
    uint32_t a;
    asm("{ .reg .u64 t; cvta.to.shared.u64 t, %1; cvt.u32.u64 %0, t; }" : "=r"(a) : "l"(p));
    return a;
}
__device__ __forceinline__ void cp_async16(uint32_t dst, const void* src) {
    asm volatile("cp.async.cg.shared.global [%0], [%1], 16;"
                 :: "r"(dst), "l"(__cvta_generic_to_global(src)) : "memory");
}
__device__ __forceinline__ void cp_commit() {
    asm volatile("cp.async.commit_group;" ::: "memory");
}
__device__ __forceinline__ void cp_wait0() {
    asm volatile("cp.async.wait_group 0;" ::: "memory");
}
__device__ __forceinline__ void ldsm_x4(uint32_t& r0, uint32_t& r1, uint32_t& r2, uint32_t& r3,
                                        uint32_t addr) {
    asm volatile("ldmatrix.sync.aligned.m8n8.x4.shared.b16 {%0,%1,%2,%3}, [%4];"
                 : "=r"(r0), "=r"(r1), "=r"(r2), "=r"(r3) : "r"(addr));
}
__device__ __forceinline__ void mma_bf16(float* c, uint32_t a0, uint32_t a1, uint32_t a2,
                                         uint32_t a3, uint32_t b0, uint32_t b1) {
    asm volatile("mma.sync.aligned.m16n8k16.row.col.f32.bf16.bf16.f32 "
                 "{%0,%1,%2,%3}, {%4,%5,%6,%7}, {%8,%9}, {%0,%1,%2,%3};"
                 : "+f"(c[0]), "+f"(c[1]), "+f"(c[2]), "+f"(c[3])
                 : "r"(a0), "r"(a1), "r"(a2), "r"(a3), "r"(b0), "r"(b1));
}

// ---------------- prep: emb -> bf16 ----------------
__global__ __launch_bounds__(256)
void prepB_kernel(const float* __restrict__ emb) {
    int i = blockIdx.x * 256 + threadIdx.x;
    g_Bm[i] = __float2bfloat16(emb[i]);
}

// ---------------- prep: emb row norms ----------------
__global__ void enorm_kernel(const float* __restrict__ emb) {
    int warp = (blockIdx.x * blockDim.x + threadIdx.x) >> 5;
    int lane = threadIdx.x & 31;
    if (warp >= Kk) return;
    const float* row = emb + (size_t)warp * Dk;
    float s = 0.f;
#pragma unroll
    for (int i = 0; i < Dk; i += 32) { float v = row[i + lane]; s += v * v; }
#pragma unroll
    for (int o = 16; o > 0; o >>= 1) s += __shfl_down_sync(0xffffffffu, s, o);
    if (lane == 0) g_enorm[warp] = s;
}

// ---------------- prep: transpose z -> [n][d] (bf16 + fp32) ----------------
__global__ void prepA_kernel(const float* __restrict__ z) {
    __shared__ float tile[32][33];
    int b = blockIdx.x >> 6;
    int t0 = (blockIdx.x & 63) * 32;
    int d0 = blockIdx.y * 32;
    int tx = threadIdx.x;
#pragma unroll
    for (int i = threadIdx.y; i < 32; i += 8)
        tile[i][tx] = z[((size_t)b * Dk + d0 + i) * Tk + t0 + tx];
    __syncthreads();
#pragma unroll
    for (int i = threadIdx.y; i < 32; i += 8) {
        int n = b * Tk + t0 + i;
        float v = tile[tx][i];
        g_A[(size_t)n * Dk + d0 + tx] = __float2bfloat16(v);
        g_zt[(size_t)n * Dk + d0 + tx] = v;
    }
}

// ---------------- pass1: bf16 HMMA GEMM, unit = 128 rows x 1024 codes ----------------
// stage s (0..63): chunk c = s>>3, kk = s&7; buf = s&3
__device__ __forceinline__ void b_stage_issue_one(uint32_t sb, int tid, int codeBase, int s) {
    int cc = s >> 3, kk = s & 7;
    int buf = s & 3;
#pragma unroll
    for (int i = 0; i < 2; i++) {
        int idx = tid + i * 256;                 // 512 x 16B = one 8KB stage
        int r = idx >> 2, ch = idx & 3;
        cp_async16(sb + SM_B + buf * B_STAGE_BYTES + (r * B_STRIDE + ch * 8) * 2,
                   g_Bm + ((size_t)(codeBase + cc * GN + r)) * Dk + kk * KW + ch * 8);
    }
}

__global__ __launch_bounds__(256, 2)
void pass1_gemm(void) {
    extern __shared__ __align__(16) char smem[];
    uint32_t sb = smem_u32(smem);

    int tid = threadIdx.x;
    int lane = tid & 31;
    int wid = tid >> 5;
    int warpN = wid & 3;      // 4 n-warps (32 cols each) == one 32-code group each
    int warpM = wid >> 2;     // 2 m-warps (64 rows each)
    int tileId = blockIdx.x & 255;
    int qc = blockIdx.x >> 8;             // 0..7
    int rowBase = tileId * GM;
    int codeBase = qc * (CPU_ * GN);      // qc * 1024

    // ---- prologue: A + pair 0 (stages 0,1) in one group ----
    {
        const __nv_bfloat16* Ag = g_A + (size_t)rowBase * Dk;
#pragma unroll
        for (int i = 0; i < 16; i++) {
            int idx = tid + i * 256;               // 4096 x 16B
            int r = idx >> 5, ch = idx & 31;
            cp_async16(sb + SM_A + (r * A_STRIDE + ch * 8) * 2, Ag + (size_t)r * Dk + ch * 8);
        }
        b_stage_issue_one(sb, tid, codeBase, 0);
        b_stage_issue_one(sb, tid, codeBase, 1);
        cp_commit();    // G0 = {A, s0, s1}
    }

    float acc[4][4][4];

    for (int p = 0; p < NPAIRS; p++) {
        cp_wait0();            // pair p fully landed (issued one pair-compute ago)
        __syncthreads();       // + all warps finished computing pair p-1 (its bufs free)
        if (p + 1 < NPAIRS) {  // issue pair p+1 into pair p-1's buffers
            b_stage_issue_one(sb, tid, codeBase, 2 * p + 2);
            b_stage_issue_one(sb, tid, codeBase, 2 * p + 3);
        }
        cp_commit();

        if ((p & 3) == 0) {    // first pair of a chunk: reset accumulators
#pragma unroll
            for (int i = 0; i < 4; i++)
#pragma unroll
                for (int j = 0; j < 4; j++)
#pragma unroll
                    for (int e = 0; e < 4; e++) acc[i][j][e] = 0.f;
        }

        // ---- compute pair p: stages 2p, 2p+1 ----
#pragma unroll
        for (int half = 0; half < 2; half++) {
            int s = 2 * p + half;
            int ksl = s & 7;                       // stage within chunk
            uint32_t bbase = sb + SM_B + (s & 3) * B_STAGE_BYTES;
#pragma unroll
            for (int kh = 0; kh < 2; kh++) {
                uint32_t af[4][4];
                uint32_t bfr[4][2];
#pragma unroll
                for (int mt = 0; mt < 4; mt++) {
                    int row = warpM * 64 + mt * 16 + (lane & 15);
                    int col = ksl * KW + kh * 16 + (lane >> 4) * 8;
                    ldsm_x4(af[mt][0], af[mt][1], af[mt][2], af[mt][3],
                            sb + SM_A + (row * A_STRIDE + col) * 2);
                }
#pragma unroll
                for (int pr = 0; pr < 2; pr++) {
                    int nrow = warpN * 32 + pr * 16 + (lane & 7) + ((lane & 16) ? 8 : 0);
                    int ncol = kh * 16 + (lane & 8);
                    uint32_t r0, r1, r2, r3;
                    ldsm_x4(r0, r1, r2, r3, bbase + (nrow * B_STRIDE + ncol) * 2);
                    bfr[pr * 2 + 0][0] = r0; bfr[pr * 2 + 0][1] = r1;
                    bfr[pr * 2 + 1][0] = r2; bfr[pr * 2 + 1][1] = r3;
                }
#pragma unroll
                for (int mt = 0; mt < 4; mt++)
#pragma unroll
                    for (int nt = 0; nt < 4; nt++)
                        mma_bf16(acc[mt][nt], af[mt][0], af[mt][1], af[mt][2], af[mt][3],
                                 bfr[nt][0], bfr[nt][1]);
            }
        }

        // ---- chunk epilogue (after last pair of chunk): octet + group mins ----
        if ((p & 3) == 3) {
            int c = p >> 2;                         // chunk within unit
            int cg = qc * CPU_ + c;                 // global chunk id (0..63)
            float en8[8];
#pragma unroll
            for (int nt = 0; nt < 4; nt++)
#pragma unroll
                for (int e = 0; e < 2; e++)
                    en8[nt * 2 + e] =
                        __ldg(&g_enorm[cg * GN + warpN * 32 + nt * 8 + (lane & 3) * 2 + e]);
#pragma unroll
            for (int mt = 0; mt < 4; mt++) {
#pragma unroll
                for (int h = 0; h < 2; h++) {
                    float v[4];
#pragma unroll
                    for (int nt = 0; nt < 4; nt++) {
                        float a = fmaf(-2.f, acc[mt][nt][h * 2 + 0], en8[nt * 2 + 0]);
                        float b = fmaf(-2.f, acc[mt][nt][h * 2 + 1], en8[nt * 2 + 1]);
                        v[nt] = fminf(a, b);
                        v[nt] = fminf(v[nt], __shfl_xor_sync(0xffffffffu, v[nt], 1));
                        v[nt] = fminf(v[nt], __shfl_xor_sync(0xffffffffu, v[nt], 2));
                    }
                    if ((lane & 3) == 0) {
                        int row = rowBase + warpM * 64 + mt * 16 + (lane >> 2) + h * 8;
                        *(float4*)(g_gmin8 + (size_t)row * 1024 + cg * 16 + warpN * 4) =
                            make_float4(v[0], v[1], v[2], v[3]);
                        g_gmin[(size_t)row * 256 + cg * 4 + warpN] =
                            fminf(fminf(v[0], v[1]), fminf(v[2], v[3]));
                    }
                }
            }
        }
    }
}

// ---------------- pass2: exact fp32 refine at octet granularity ----------------
__global__ __launch_bounds__(256)
void refine_kernel(const float* __restrict__ emb, float* __restrict__ idx_out) {
    __shared__ __align__(16) float zsh[8][256];
    int lane = threadIdx.x & 31;
    int wid = threadIdx.x >> 5;
    int n = blockIdx.x * 8 + wid;

    float zn = 0.f;
#pragma unroll
    for (int i = 0; i < 8; i++) {
        float v = g_zt[(size_t)n * Dk + lane + 32 * i];
        zsh[wid][lane + 32 * i] = v;
        zn = fmaf(v, v, zn);
    }
#pragma unroll
    for (int o = 16; o > 0; o >>= 1) zn += __shfl_xor_sync(0xffffffffu, zn, o);
    __syncwarp();

    float gmv[8];
    float m = 3.4e38f;
#pragma unroll
    for (int i = 0; i < 8; i++) {
        gmv[i] = g_gmin[(size_t)n * 256 + lane + 32 * i];
        m = fminf(m, gmv[i]);
    }
#pragma unroll
    for (int o = 16; o > 0; o >>= 1) m = fminf(m, __shfl_xor_sync(0xffffffffu, m, o));
    float thr = m + TAU;

    float bd = 3.4e38f;
    int bi = 0x7fffffff;
    int cq = lane >> 2;          // code within octet
    int p = lane & 3;            // quarter of d
    const float4* zv4 = (const float4*)zsh[wid];

#pragma unroll 1
    for (int i = 0; i < 8; i++) {
        unsigned mask = __ballot_sync(0xffffffffu, gmv[i] <= thr);
        while (mask) {
            int b = __ffs(mask) - 1;
            mask &= mask - 1;
            int g = i * 32 + b;
            float4 o4 = *(const float4*)(g_gmin8 + (size_t)n * 1024 + g * 4);
            float om[4] = {o4.x, o4.y, o4.z, o4.w};
#pragma unroll 1
            for (int o = 0; o < 4; o++) {
                if (om[o] > thr) continue;
                int k = (g * 4 + o) * 8 + cq;
                const float4* er4 = (const float4*)(emb + (size_t)k * Dk);
                float s0 = 0.f, s1 = 0.f, s2 = 0.f, s3 = 0.f;
#pragma unroll
                for (int j = 0; j < 16; j++) {
                    float4 e4 = er4[p + 4 * j];
                    float4 z4 = zv4[p + 4 * j];
                    s0 = fmaf(z4.x, e4.x, s0);
                    s1 = fmaf(z4.y, e4.y, s1);
                    s2 = fmaf(z4.z, e4.z, s2);
                    s3 = fmaf(z4.w, e4.w, s3);
                }
                float dot = (s0 + s1) + (s2 + s3);
                dot += __shfl_xor_sync(0xffffffffu, dot, 1);
                dot += __shfl_xor_sync(0xffffffffu, dot, 2);
                float d = (zn + g_enorm[k]) - 2.0f * dot;
                if (d < bd || (d == bd && k < bi)) { bd = d; bi = k; }
            }
        }
    }
#pragma unroll
    for (int o = 16; o > 0; o >>= 1) {
        float od = __shfl_xor_sync(0xffffffffu, bd, o);
        int   oi = __shfl_xor_sync(0xffffffffu, bi, o);
        if (od < bd || (od == bd && oi < bi)) { bd = od; bi = oi; }
    }
    if (lane == 0) {
        g_idx[n] = bi;
        if (idx_out) idx_out[n] = (float)bi;
    }
}

// ---------------- gather quantized + loss partials (float4) ----------------
__global__ __launch_bounds__(256)
void quant_loss_kernel(const float* __restrict__ z, const float* __restrict__ emb,
                       float* __restrict__ qout) {
    __shared__ float wsum[8];
    int base = blockIdx.x * 1024 + threadIdx.x * 4;
    int t = base & 2047;
    int d = (base >> 11) & 255;
    int b = base >> 19;
    int n = b * 2048 + t;
    int4 iv = *(const int4*)(g_idx + n);
    float4 zv = *(const float4*)(z + base);
    float4 q;
    q.x = emb[(size_t)iv.x * Dk + d];
    q.y = emb[(size_t)iv.y * Dk + d];
    q.z = emb[(size_t)iv.z * Dk + d];
    q.w = emb[(size_t)iv.w * Dk + d];
    *(float4*)(qout + base) = q;
    float dx = q.x - zv.x, dy = q.y - zv.y, dz = q.z - zv.z, dw = q.w - zv.w;
    float s = dx * dx + dy * dy + dz * dz + dw * dw;
#pragma unroll
    for (int o = 16; o > 0; o >>= 1) s += __shfl_xor_sync(0xffffffffu, s, o);
    if ((threadIdx.x & 31) == 0) wsum[threadIdx.x >> 5] = s;
    __syncthreads();
    if (threadIdx.x == 0) {
        double tot = 0.0;
#pragma unroll
        for (int w = 0; w < 8; w++) tot += (double)wsum[w];
        g_losspart[blockIdx.x] = tot;
    }
}

__global__ void loss_kernel(float* __restrict__ loss_out) {
    __shared__ double red[256];
    double s = 0.0;
    for (int i = threadIdx.x; i < QCOUNT / 1024; i += 256) s += g_losspart[i];
    red[threadIdx.x] = s;
    __syncthreads();
#pragma unroll
    for (int o = 128; o > 0; o >>= 1) {
        if (threadIdx.x < o) red[threadIdx.x] += red[threadIdx.x + o];
        __syncthreads();
    }
    if (threadIdx.x == 0)
        loss_out[0] = (float)(1.25 * (red[0] / (double)QCOUNT));
}

// ---------------- host launch ----------------
extern "C" void kernel_launch(void* const* d_in, const int* in_sizes, int n_in,
                              void* d_out, int out_size) {
    const float* z   = (const float*)d_in[0];
    const float* emb = (const float*)d_in[1];
    float* out = (float*)d_out;

    float* qout     = out;
    float* loss_out = nullptr;
    float* idx_out  = nullptr;
    if (out_size >= QCOUNT + 1 + Nk) {          // [quantized | loss | idx]
        loss_out = out + QCOUNT;
        idx_out  = out + QCOUNT + 1;
    } else if (out_size == QCOUNT + Nk) {
        idx_out = out + QCOUNT;
    } else if (out_size == QCOUNT + 1) {
        loss_out = out + QCOUNT;
    }

    static bool attr_set = false;
    if (!attr_set) {
        cudaFuncSetAttribute(pass1_gemm, cudaFuncAttributeMaxDynamicSharedMemorySize, SMEM_TOTAL);
        attr_set = true;
    }

    prepB_kernel<<<(Kk * Dk) / 256, 256>>>(emb);            // launch 0
    enorm_kernel<<<Kk / 8, 256>>>(emb);                     // launch 1
    prepA_kernel<<<dim3(Bk * (Tk / 32), Dk / 32), dim3(32, 8)>>>(z);  // launch 2
    pass1_gemm<<<256 * CPU_, 256, SMEM_TOTAL>>>();          // launch 3 (ncu slot)
    refine_kernel<<<Nk / 8, 256>>>(emb, idx_out);           // launch 4
    quant_loss_kernel<<<QCOUNT / 1024, 256>>>(z, emb, qout);// launch 5
    if (loss_out) loss_kernel<<<1, 256>>>(loss_out);        // launch 6
}